// round 1
// baseline (speedup 1.0000x reference)
#include <cuda_runtime.h>
#include <math.h>

// Problem constants (match reference)
#define N_USER  100000
#define N_ITEM  50000
#define N_NODES (N_USER + N_ITEM)   // 150000
#define N_EDGES 2000000
#define EMB     64
#define BATCH   2048
#define SCAN_BS 1024
#define NBLK_SCAN ((N_NODES + SCAN_BS - 1) / SCAN_BS)  // 147

// ---------------- Device scratch (static; no runtime allocation) ----------------
__device__ float g_emb0[(size_t)N_NODES * EMB];
__device__ float g_emb1[(size_t)N_NODES * EMB];
__device__ float g_acc [(size_t)N_NODES * EMB];
__device__ int   g_rowstart[N_NODES + 1];
__device__ int   g_cnt[N_NODES];          // histogram, then reused as scatter cursor
__device__ int   g_blocksums[256];
__device__ int   g_blockoffs[256];
__device__ int   g_colsorted[N_EDGES];
__device__ float g_valsorted[N_EDGES];

// ---------------- 1. concat user/item emb -> emb0, acc ----------------
__global__ void concat_kernel(const float4* __restrict__ ue,
                              const float4* __restrict__ ie) {
    int i = blockIdx.x * blockDim.x + threadIdx.x;   // float4 index
    const int total = N_NODES * (EMB / 4);
    if (i >= total) return;
    int node = i >> 4;          // /16 float4s per node
    int d4   = i & 15;
    float4 v = (node < N_USER) ? ue[node * 16 + d4]
                               : ie[(node - N_USER) * 16 + d4];
    ((float4*)g_emb0)[i] = v;
    ((float4*)g_acc)[i]  = v;
}

// ---------------- 2. CSR build ----------------
__global__ void zero_cnt_kernel() {
    int i = blockIdx.x * blockDim.x + threadIdx.x;
    if (i < N_NODES) g_cnt[i] = 0;
}

__global__ void hist_kernel(const int* __restrict__ rows) {
    int e = blockIdx.x * blockDim.x + threadIdx.x;
    if (e < N_EDGES) atomicAdd(&g_cnt[rows[e]], 1);
}

__global__ void scanA_kernel() {
    __shared__ int s[SCAN_BS];
    int t = threadIdx.x;
    int i = blockIdx.x * SCAN_BS + t;
    int x = (i < N_NODES) ? g_cnt[i] : 0;
    s[t] = x;
    __syncthreads();
    #pragma unroll
    for (int off = 1; off < SCAN_BS; off <<= 1) {
        int v = (t >= off) ? s[t - off] : 0;
        __syncthreads();
        s[t] += v;
        __syncthreads();
    }
    if (i < N_NODES) g_rowstart[i] = s[t] - x;      // exclusive within block
    if (t == SCAN_BS - 1) g_blocksums[blockIdx.x] = s[t];
}

__global__ void scanB_kernel() {
    // tiny: single thread scans 147 block sums
    if (threadIdx.x == 0 && blockIdx.x == 0) {
        int run = 0;
        for (int b = 0; b < NBLK_SCAN; b++) {
            g_blockoffs[b] = run;
            run += g_blocksums[b];
        }
        g_rowstart[N_NODES] = run;   // == N_EDGES
    }
}

__global__ void scanC_kernel() {
    int i = blockIdx.x * blockDim.x + threadIdx.x;
    if (i < N_NODES) {
        int v = g_rowstart[i] + g_blockoffs[i / SCAN_BS];
        g_rowstart[i] = v;
        g_cnt[i] = v;                // cursor for scatter
    }
}

__global__ void scatter_kernel(const int* __restrict__ rows,
                               const int* __restrict__ cols,
                               const float* __restrict__ vals) {
    int e = blockIdx.x * blockDim.x + threadIdx.x;
    if (e >= N_EDGES) return;
    int r = rows[e];
    int pos = atomicAdd(&g_cnt[r], 1);
    g_colsorted[pos] = cols[e];
    g_valsorted[pos] = vals[e];
}

// ---------------- 3. SpMM: one warp per row, float2 per lane ----------------
// dir==0: in=g_emb0, out=g_emb1 ; dir==1: in=g_emb1, out=g_emb0
__global__ void spmm_kernel(int dir) {
    int row = blockIdx.x * (blockDim.x >> 5) + (threadIdx.x >> 5);
    if (row >= N_NODES) return;
    const float2* __restrict__ in2 =
        (const float2*)(dir ? g_emb1 : g_emb0);
    float2* __restrict__ out2 = (float2*)(dir ? g_emb0 : g_emb1);
    int lane = threadIdx.x & 31;

    int s = g_rowstart[row];
    int e = g_rowstart[row + 1];

    float ax = 0.f, ay = 0.f;
    int j = s;
    // 4-edge unroll: 4 independent gathers in flight (MLP)
    for (; j + 4 <= e; j += 4) {
        int c0 = g_colsorted[j + 0];
        int c1 = g_colsorted[j + 1];
        int c2 = g_colsorted[j + 2];
        int c3 = g_colsorted[j + 3];
        float v0 = g_valsorted[j + 0];
        float v1 = g_valsorted[j + 1];
        float v2 = g_valsorted[j + 2];
        float v3 = g_valsorted[j + 3];
        float2 f0 = in2[c0 * 32 + lane];
        float2 f1 = in2[c1 * 32 + lane];
        float2 f2 = in2[c2 * 32 + lane];
        float2 f3 = in2[c3 * 32 + lane];
        ax += v0 * f0.x; ay += v0 * f0.y;
        ax += v1 * f1.x; ay += v1 * f1.y;
        ax += v2 * f2.x; ay += v2 * f2.y;
        ax += v3 * f3.x; ay += v3 * f3.y;
    }
    for (; j < e; j++) {
        int c = g_colsorted[j];
        float v = g_valsorted[j];
        float2 f = in2[c * 32 + lane];
        ax += v * f.x; ay += v * f.y;
    }

    float2 o; o.x = ax; o.y = ay;
    out2[row * 32 + lane] = o;

    float2* ap = (float2*)g_acc + row * 32 + lane;
    float2 av = *ap;
    av.x += ax; av.y += ay;
    *ap = av;
}

// ---------------- 4. gather + GEMM (u @ i.T) + sigmoid ----------------
// 64x64 output tile per block, 256 threads, each thread 4x4. K=64 fully in smem.
__global__ void bpr_out_kernel(const int* __restrict__ users,
                               const int* __restrict__ items,
                               float* __restrict__ out) {
    __shared__ float Us[64][68];   // [row][k], pad 68 (16B-aligned rows, bank-spread)
    __shared__ float Is[64][68];
    int t   = threadIdx.x;
    int bu0 = blockIdx.y * 64;
    int bi0 = blockIdx.x * 64;

    // load both 64x64 operand tiles (scaled by 0.25 each -> dot / 16)
    #pragma unroll
    for (int i = 0; i < 4; i++) {
        int idx = t + i * 256;      // 0..1023
        int r   = idx >> 4;         // 0..63
        int kq  = idx & 15;         // 0..15 (float4 column)
        int urow = users[bu0 + r];
        float4 v = *(const float4*)&g_acc[(size_t)urow * EMB + kq * 4];
        v.x *= 0.25f; v.y *= 0.25f; v.z *= 0.25f; v.w *= 0.25f;
        *(float4*)&Us[r][kq * 4] = v;
        int irow = N_USER + items[bi0 + r];
        float4 w = *(const float4*)&g_acc[(size_t)irow * EMB + kq * 4];
        w.x *= 0.25f; w.y *= 0.25f; w.z *= 0.25f; w.w *= 0.25f;
        *(float4*)&Is[r][kq * 4] = w;
    }
    __syncthreads();

    int tx = t & 15;     // col quad
    int ty = t >> 4;     // row quad
    float acc[4][4];
    #pragma unroll
    for (int r = 0; r < 4; r++)
        #pragma unroll
        for (int c = 0; c < 4; c++) acc[r][c] = 0.f;

    #pragma unroll
    for (int k = 0; k < 64; k += 4) {
        float4 a[4], b[4];
        #pragma unroll
        for (int r = 0; r < 4; r++) a[r] = *(const float4*)&Us[ty * 4 + r][k];
        #pragma unroll
        for (int c = 0; c < 4; c++) b[c] = *(const float4*)&Is[tx * 4 + c][k];
        #pragma unroll
        for (int r = 0; r < 4; r++)
            #pragma unroll
            for (int c = 0; c < 4; c++)
                acc[r][c] += a[r].x * b[c].x + a[r].y * b[c].y
                           + a[r].z * b[c].z + a[r].w * b[c].w;
    }

    #pragma unroll
    for (int r = 0; r < 4; r++) {
        int orow = bu0 + ty * 4 + r;
        float4 o;
        o.x = 1.f / (1.f + expf(-acc[r][0]));
        o.y = 1.f / (1.f + expf(-acc[r][1]));
        o.z = 1.f / (1.f + expf(-acc[r][2]));
        o.w = 1.f / (1.f + expf(-acc[r][3]));
        *(float4*)&out[(size_t)orow * BATCH + bi0 + tx * 4] = o;
    }
}

// ---------------- launch ----------------
extern "C" void kernel_launch(void* const* d_in, const int* in_sizes, int n_in,
                              void* d_out, int out_size) {
    const float* user_emb = (const float*)d_in[0];
    const float* item_emb = (const float*)d_in[1];
    const float* adj_vals = (const float*)d_in[2];
    const int*   adj_rows = (const int*)d_in[3];
    const int*   adj_cols = (const int*)d_in[4];
    const int*   users    = (const int*)d_in[5];
    const int*   items    = (const int*)d_in[6];
    float*       out      = (float*)d_out;

    // 1. concat + init acc
    {
        int total = N_NODES * (EMB / 4);
        concat_kernel<<<(total + 255) / 256, 256>>>(
            (const float4*)user_emb, (const float4*)item_emb);
    }

    // 2. CSR build
    zero_cnt_kernel<<<(N_NODES + 255) / 256, 256>>>();
    hist_kernel<<<(N_EDGES + 255) / 256, 256>>>(adj_rows);
    scanA_kernel<<<NBLK_SCAN, SCAN_BS>>>();
    scanB_kernel<<<1, 32>>>();
    scanC_kernel<<<(N_NODES + 255) / 256, 256>>>();
    scatter_kernel<<<(N_EDGES + 255) / 256, 256>>>(adj_rows, adj_cols, adj_vals);

    // 3. three propagation layers (ping-pong)
    {
        int warps_per_block = 8;
        int blocks = (N_NODES + warps_per_block - 1) / warps_per_block;
        spmm_kernel<<<blocks, warps_per_block * 32>>>(0); // emb0 -> emb1
        spmm_kernel<<<blocks, warps_per_block * 32>>>(1); // emb1 -> emb0
        spmm_kernel<<<blocks, warps_per_block * 32>>>(0); // emb0 -> emb1
    }

    // 4. output GEMM + sigmoid
    {
        dim3 grid(BATCH / 64, BATCH / 64);
        bpr_out_kernel<<<grid, 256>>>(users, items, out);
    }
}

// round 2
// speedup vs baseline: 1.5622x; 1.5622x over previous
#include <cuda_runtime.h>
#include <math.h>

#define N_USER  100000
#define N_ITEM  50000
#define N_NODES (N_USER + N_ITEM)      // 150000
#define N_EDGES 2000000
#define EMB     64
#define BATCH   2048
#define SEL     (2 * BATCH)            // 4096 selected nodes
#define SCAN_BS 1024
#define NBLK_SCAN ((N_NODES + SCAN_BS - 1) / SCAN_BS)   // 147

// ---------------- Device scratch (static; no runtime allocation) ----------------
__device__ float g_e1 [(size_t)N_NODES * EMB];   // layer-1 embeddings (all nodes)
__device__ float g_e2 [(size_t)N_NODES * EMB];   // layer-2 embeddings (flagged rows only)
__device__ float g_e3c[(size_t)SEL * EMB];       // layer-3, compact over selected nodes
__device__ float g_sel[(size_t)SEL * EMB];       // 0.25*(e0+e1+e2+e3) at selected nodes
__device__ int   g_rowstart[N_NODES + 1];
__device__ int   g_cnt[N_NODES];                 // histogram, then scatter cursor
__device__ unsigned char g_flag[N_NODES];        // layer-2 frontier
__device__ int2  g_edge[N_EDGES];                // (col, val-as-int) interleaved
__device__ int   g_blocksums[256];
__device__ int   g_blockoffs[256];

// ---------------- CSR build ----------------
__global__ void zero_kernel() {
    int i = blockIdx.x * blockDim.x + threadIdx.x;
    if (i < N_NODES) { g_cnt[i] = 0; g_flag[i] = 0; }
}

__global__ void hist_kernel(const int4* __restrict__ rows4) {
    int e4 = blockIdx.x * blockDim.x + threadIdx.x;
    if (e4 < N_EDGES / 4) {
        int4 r = rows4[e4];
        atomicAdd(&g_cnt[r.x], 1);
        atomicAdd(&g_cnt[r.y], 1);
        atomicAdd(&g_cnt[r.z], 1);
        atomicAdd(&g_cnt[r.w], 1);
    }
}

__global__ void scanA_kernel() {
    __shared__ int s[SCAN_BS];
    int t = threadIdx.x;
    int i = blockIdx.x * SCAN_BS + t;
    int x = (i < N_NODES) ? g_cnt[i] : 0;
    s[t] = x;
    __syncthreads();
    #pragma unroll
    for (int off = 1; off < SCAN_BS; off <<= 1) {
        int v = (t >= off) ? s[t - off] : 0;
        __syncthreads();
        s[t] += v;
        __syncthreads();
    }
    if (i < N_NODES) g_rowstart[i] = s[t] - x;      // exclusive within block
    if (t == SCAN_BS - 1) g_blocksums[blockIdx.x] = s[t];
}

__global__ void scanB_kernel() {
    __shared__ int s[256];
    int t = threadIdx.x;
    int x = (t < NBLK_SCAN) ? g_blocksums[t] : 0;
    s[t] = x;
    __syncthreads();
    #pragma unroll
    for (int off = 1; off < 256; off <<= 1) {
        int v = (t >= off) ? s[t - off] : 0;
        __syncthreads();
        s[t] += v;
        __syncthreads();
    }
    if (t < NBLK_SCAN) g_blockoffs[t] = s[t] - x;   // exclusive
    if (t == 255) g_rowstart[N_NODES] = s[t];       // == N_EDGES
}

__global__ void scanC_kernel() {
    int i = blockIdx.x * blockDim.x + threadIdx.x;
    if (i < N_NODES) {
        int v = g_rowstart[i] + g_blockoffs[i / SCAN_BS];
        g_rowstart[i] = v;
        g_cnt[i] = v;                // cursor for scatter
    }
}

__global__ void scatter_kernel(const int* __restrict__ rows,
                               const int* __restrict__ cols,
                               const float* __restrict__ vals) {
    int e = blockIdx.x * blockDim.x + threadIdx.x;
    if (e >= N_EDGES) return;
    int r = rows[e];
    int pos = atomicAdd(&g_cnt[r], 1);
    g_edge[pos] = make_int2(cols[e], __float_as_int(vals[e]));
}

// ---------------- Layer-2 frontier flags ----------------
__global__ void flagmark_kernel(const int* __restrict__ users,
                                const int* __restrict__ items) {
    int b = blockIdx.x * blockDim.x + threadIdx.x;
    if (b >= SEL) return;
    int r = (b < BATCH) ? users[b] : N_USER + items[b - BATCH];
    g_flag[r] = 1;
    int s = g_rowstart[r], e = g_rowstart[r + 1];
    for (int j = s; j < e; j++) g_flag[g_edge[j].x] = 1;
}

// ---------------- SpMM helpers ----------------
// 16 lanes per row, float4 per lane. 256-thread block = 16 rows.
__device__ __forceinline__ float4 row_reduce(const float4* __restrict__ in,
                                             int s, int e, int lane) {
    float4 a = make_float4(0.f, 0.f, 0.f, 0.f);
    int j = s;
    for (; j + 4 <= e; j += 4) {
        int2 E0 = g_edge[j], E1 = g_edge[j + 1], E2 = g_edge[j + 2], E3 = g_edge[j + 3];
        float4 f0 = in[(size_t)E0.x * 16 + lane];
        float4 f1 = in[(size_t)E1.x * 16 + lane];
        float4 f2 = in[(size_t)E2.x * 16 + lane];
        float4 f3 = in[(size_t)E3.x * 16 + lane];
        float v0 = __int_as_float(E0.y), v1 = __int_as_float(E1.y);
        float v2 = __int_as_float(E2.y), v3 = __int_as_float(E3.y);
        a.x += v0 * f0.x; a.y += v0 * f0.y; a.z += v0 * f0.z; a.w += v0 * f0.w;
        a.x += v1 * f1.x; a.y += v1 * f1.y; a.z += v1 * f1.z; a.w += v1 * f1.w;
        a.x += v2 * f2.x; a.y += v2 * f2.y; a.z += v2 * f2.z; a.w += v2 * f2.w;
        a.x += v3 * f3.x; a.y += v3 * f3.y; a.z += v3 * f3.z; a.w += v3 * f3.w;
    }
    for (; j < e; j++) {
        int2 E = g_edge[j];
        float4 f = in[(size_t)E.x * 16 + lane];
        float v = __int_as_float(E.y);
        a.x += v * f.x; a.y += v * f.y; a.z += v * f.z; a.w += v * f.w;
    }
    return a;
}

// Layer 1: gather directly from user_emb / item_emb (no concat), full node set.
__global__ void spmm1_kernel(const float4* __restrict__ ue,
                             const float4* __restrict__ ie) {
    int gid = blockIdx.x * blockDim.x + threadIdx.x;
    int row = gid >> 4, lane = gid & 15;
    if (row >= N_NODES) return;
    int s = g_rowstart[row], e = g_rowstart[row + 1];
    float4 a = make_float4(0.f, 0.f, 0.f, 0.f);
    int j = s;
    for (; j + 4 <= e; j += 4) {
        int2 E0 = g_edge[j], E1 = g_edge[j + 1], E2 = g_edge[j + 2], E3 = g_edge[j + 3];
        const float4* p0 = (E0.x < N_USER) ? ue + (size_t)E0.x * 16 : ie + (size_t)(E0.x - N_USER) * 16;
        const float4* p1 = (E1.x < N_USER) ? ue + (size_t)E1.x * 16 : ie + (size_t)(E1.x - N_USER) * 16;
        const float4* p2 = (E2.x < N_USER) ? ue + (size_t)E2.x * 16 : ie + (size_t)(E2.x - N_USER) * 16;
        const float4* p3 = (E3.x < N_USER) ? ue + (size_t)E3.x * 16 : ie + (size_t)(E3.x - N_USER) * 16;
        float4 f0 = p0[lane], f1 = p1[lane], f2 = p2[lane], f3 = p3[lane];
        float v0 = __int_as_float(E0.y), v1 = __int_as_float(E1.y);
        float v2 = __int_as_float(E2.y), v3 = __int_as_float(E3.y);
        a.x += v0 * f0.x; a.y += v0 * f0.y; a.z += v0 * f0.z; a.w += v0 * f0.w;
        a.x += v1 * f1.x; a.y += v1 * f1.y; a.z += v1 * f1.z; a.w += v1 * f1.w;
        a.x += v2 * f2.x; a.y += v2 * f2.y; a.z += v2 * f2.z; a.w += v2 * f2.w;
        a.x += v3 * f3.x; a.y += v3 * f3.y; a.z += v3 * f3.z; a.w += v3 * f3.w;
    }
    for (; j < e; j++) {
        int2 E = g_edge[j];
        const float4* p = (E.x < N_USER) ? ue + (size_t)E.x * 16 : ie + (size_t)(E.x - N_USER) * 16;
        float4 f = p[lane];
        float v = __int_as_float(E.y);
        a.x += v * f.x; a.y += v * f.y; a.z += v * f.z; a.w += v * f.w;
    }
    ((float4*)g_e1)[(size_t)row * 16 + lane] = a;
}

// Layer 2: only flagged rows (frontier of selected nodes).
__global__ void spmm2_kernel() {
    int gid = blockIdx.x * blockDim.x + threadIdx.x;
    int row = gid >> 4, lane = gid & 15;
    if (row >= N_NODES) return;
    if (!g_flag[row]) return;
    int s = g_rowstart[row], e = g_rowstart[row + 1];
    float4 a = row_reduce((const float4*)g_e1, s, e, lane);
    ((float4*)g_e2)[(size_t)row * 16 + lane] = a;
}

// Layer 3: only the 4096 selected nodes, compact output.
__global__ void spmm3_kernel(const int* __restrict__ users,
                             const int* __restrict__ items) {
    int gid = blockIdx.x * blockDim.x + threadIdx.x;
    int b = gid >> 4, lane = gid & 15;
    if (b >= SEL) return;
    int row = (b < BATCH) ? users[b] : N_USER + items[b - BATCH];
    int s = g_rowstart[row], e = g_rowstart[row + 1];
    float4 a = row_reduce((const float4*)g_e2, s, e, lane);
    ((float4*)g_e3c)[(size_t)b * 16 + lane] = a;
}

// Combine the 4 layer embeddings (mean) at the 4096 selected nodes.
__global__ void sel_combine_kernel(const float4* __restrict__ ue,
                                   const float4* __restrict__ ie,
                                   const int* __restrict__ users,
                                   const int* __restrict__ items) {
    int gid = blockIdx.x * blockDim.x + threadIdx.x;
    int b = gid >> 4, lane = gid & 15;
    if (b >= SEL) return;
    int row; float4 e0;
    if (b < BATCH) { int u = users[b]; row = u; e0 = ue[(size_t)u * 16 + lane]; }
    else { int it = items[b - BATCH]; row = N_USER + it; e0 = ie[(size_t)it * 16 + lane]; }
    float4 r1 = ((const float4*)g_e1)[(size_t)row * 16 + lane];
    float4 r2 = ((const float4*)g_e2)[(size_t)row * 16 + lane];
    float4 r3 = ((const float4*)g_e3c)[(size_t)b * 16 + lane];
    float4 o;
    o.x = 0.25f * (e0.x + r1.x + r2.x + r3.x);
    o.y = 0.25f * (e0.y + r1.y + r2.y + r3.y);
    o.z = 0.25f * (e0.z + r1.z + r2.z + r3.z);
    o.w = 0.25f * (e0.w + r1.w + r2.w + r3.w);
    ((float4*)g_sel)[(size_t)b * 16 + lane] = o;
}

// ---------------- GEMM (u @ i.T) + sigmoid ----------------
// 64x64 output tile per block, 256 threads, each thread 4x4. K=64 fully in smem.
__global__ void bpr_out_kernel(float* __restrict__ out) {
    __shared__ float Us[64][68];
    __shared__ float Is[64][68];
    int t   = threadIdx.x;
    int bu0 = blockIdx.y * 64;
    int bi0 = blockIdx.x * 64;

    const float4* sel4 = (const float4*)g_sel;
    #pragma unroll
    for (int i = 0; i < 4; i++) {
        int idx = t + i * 256;      // 0..1023
        int r   = idx >> 4;         // 0..63
        int kq  = idx & 15;         // 0..15
        *(float4*)&Us[r][kq * 4] = sel4[(size_t)(bu0 + r) * 16 + kq];
        *(float4*)&Is[r][kq * 4] = sel4[(size_t)(BATCH + bi0 + r) * 16 + kq];
    }
    __syncthreads();

    int tx = t & 15, ty = t >> 4;
    float acc[4][4];
    #pragma unroll
    for (int r = 0; r < 4; r++)
        #pragma unroll
        for (int c = 0; c < 4; c++) acc[r][c] = 0.f;

    #pragma unroll
    for (int k = 0; k < 64; k += 4) {
        float4 a[4], b[4];
        #pragma unroll
        for (int r = 0; r < 4; r++) a[r] = *(const float4*)&Us[ty * 4 + r][k];
        #pragma unroll
        for (int c = 0; c < 4; c++) b[c] = *(const float4*)&Is[tx * 4 + c][k];
        #pragma unroll
        for (int r = 0; r < 4; r++)
            #pragma unroll
            for (int c = 0; c < 4; c++)
                acc[r][c] += a[r].x * b[c].x + a[r].y * b[c].y
                           + a[r].z * b[c].z + a[r].w * b[c].w;
    }

    #pragma unroll
    for (int r = 0; r < 4; r++) {
        int orow = bu0 + ty * 4 + r;
        float4 o;
        o.x = 1.f / (1.f + expf(-acc[r][0]));
        o.y = 1.f / (1.f + expf(-acc[r][1]));
        o.z = 1.f / (1.f + expf(-acc[r][2]));
        o.w = 1.f / (1.f + expf(-acc[r][3]));
        *(float4*)&out[(size_t)orow * BATCH + bi0 + tx * 4] = o;
    }
}

// ---------------- launch ----------------
extern "C" void kernel_launch(void* const* d_in, const int* in_sizes, int n_in,
                              void* d_out, int out_size) {
    const float* user_emb = (const float*)d_in[0];
    const float* item_emb = (const float*)d_in[1];
    const float* adj_vals = (const float*)d_in[2];
    const int*   adj_rows = (const int*)d_in[3];
    const int*   adj_cols = (const int*)d_in[4];
    const int*   users    = (const int*)d_in[5];
    const int*   items    = (const int*)d_in[6];
    float*       out      = (float*)d_out;

    // CSR build
    zero_kernel<<<(N_NODES + 255) / 256, 256>>>();
    hist_kernel<<<(N_EDGES / 4 + 255) / 256, 256>>>((const int4*)adj_rows);
    scanA_kernel<<<NBLK_SCAN, SCAN_BS>>>();
    scanB_kernel<<<1, 256>>>();
    scanC_kernel<<<(N_NODES + 255) / 256, 256>>>();
    scatter_kernel<<<(N_EDGES + 255) / 256, 256>>>(adj_rows, adj_cols, adj_vals);

    // Layer 1: full
    {
        int threads = N_NODES * 16;
        spmm1_kernel<<<(threads + 255) / 256, 256>>>(
            (const float4*)user_emb, (const float4*)item_emb);
    }
    // Frontier flags for layer 2
    flagmark_kernel<<<(SEL + 255) / 256, 256>>>(users, items);
    // Layer 2: flagged rows only
    {
        int threads = N_NODES * 16;
        spmm2_kernel<<<(threads + 255) / 256, 256>>>();
    }
    // Layer 3: selected nodes only
    spmm3_kernel<<<(SEL * 16) / 256, 256>>>(users, items);
    // Layer mean at selected nodes
    sel_combine_kernel<<<(SEL * 16) / 256, 256>>>(
        (const float4*)user_emb, (const float4*)item_emb, users, items);

    // Output GEMM + sigmoid
    {
        dim3 grid(BATCH / 64, BATCH / 64);
        bpr_out_kernel<<<grid, 256>>>(out);
    }
}

// round 3
// speedup vs baseline: 1.6996x; 1.0879x over previous
#include <cuda_runtime.h>
#include <cuda_fp16.h>
#include <math.h>

#define N_USER  100000
#define N_ITEM  50000
#define N_NODES (N_USER + N_ITEM)      // 150000
#define N_EDGES 2000000
#define EMB     64
#define BATCH   2048
#define SEL     (2 * BATCH)            // 4096 selected nodes
#define SCAN_BS 1024
#define NBLK_SCAN ((N_NODES + SCAN_BS - 1) / SCAN_BS)   // 147

// ---------------- Device scratch (static; no runtime allocation) ----------------
__device__ __half g_emb_h[(size_t)N_NODES * EMB];  // fp16 concat of user+item emb
__device__ __half g_e1h  [(size_t)N_NODES * EMB];  // layer-1 (fp16)
__device__ __half g_e2h  [(size_t)N_NODES * EMB];  // layer-2 (fp16, flagged rows)
__device__ float  g_sel  [(size_t)SEL * EMB];      // layer mean at selected nodes (fp32)
__device__ int    g_rowstart[N_NODES + 1];
__device__ int    g_cnt[N_NODES];                  // histogram, then scatter cursor
__device__ unsigned char g_flag[N_NODES];          // layer-2 frontier
__device__ int2   g_edge[N_EDGES];                 // (col, val-as-int)
__device__ int    g_blocksums[256];

// ---------------- 1. zero counters + convert embeddings to fp16 ----------------
// grid covers N_NODES*16 threads (one float4 -> half4 each); also zeroes cnt/flag.
__global__ void zero_convert_kernel(const float4* __restrict__ ue,
                                    const float4* __restrict__ ie) {
    int i = blockIdx.x * blockDim.x + threadIdx.x;
    if (i < N_NODES) { g_cnt[i] = 0; g_flag[i] = 0; }
    if (i >= N_NODES * 16) return;
    int node = i >> 4, q = i & 15;
    float4 v = (node < N_USER) ? ue[(size_t)node * 16 + q]
                               : ie[(size_t)(node - N_USER) * 16 + q];
    __half2 h0 = __float22half2_rn(make_float2(v.x, v.y));
    __half2 h1 = __float22half2_rn(make_float2(v.z, v.w));
    uint2 packed;
    packed.x = *reinterpret_cast<unsigned*>(&h0);
    packed.y = *reinterpret_cast<unsigned*>(&h1);
    ((uint2*)g_emb_h)[i] = packed;
}

// ---------------- 2. CSR build ----------------
__global__ void hist_kernel(const int4* __restrict__ rows4) {
    int e4 = blockIdx.x * blockDim.x + threadIdx.x;
    if (e4 < N_EDGES / 4) {
        int4 r = rows4[e4];
        atomicAdd(&g_cnt[r.x], 1);
        atomicAdd(&g_cnt[r.y], 1);
        atomicAdd(&g_cnt[r.z], 1);
        atomicAdd(&g_cnt[r.w], 1);
    }
}

__global__ void scanA_kernel() {
    __shared__ int s[SCAN_BS];
    int t = threadIdx.x;
    int i = blockIdx.x * SCAN_BS + t;
    int x = (i < N_NODES) ? g_cnt[i] : 0;
    s[t] = x;
    __syncthreads();
    #pragma unroll
    for (int off = 1; off < SCAN_BS; off <<= 1) {
        int v = (t >= off) ? s[t - off] : 0;
        __syncthreads();
        s[t] += v;
        __syncthreads();
    }
    if (i < N_NODES) g_rowstart[i] = s[t] - x;      // exclusive within block
    if (t == SCAN_BS - 1) g_blocksums[blockIdx.x] = s[t];
}

// scanC with inlined scan of the 147 block sums (replaces scanB launch).
// Each 256-thread block covers 256 nodes, all within ONE scanA block region,
// so every thread here needs the same single exclusive block offset.
__global__ void scanC_kernel() {
    __shared__ int s[256];
    int t = threadIdx.x;
    int x = (t < NBLK_SCAN) ? g_blocksums[t] : 0;
    s[t] = x;
    __syncthreads();
    #pragma unroll
    for (int off = 1; off < 256; off <<= 1) {
        int v = (t >= off) ? s[t - off] : 0;
        __syncthreads();
        s[t] += v;
        __syncthreads();
    }
    // exclusive offset for scanA-block k is s[k] - blocksums[k]
    int i = blockIdx.x * 256 + t;
    if (i < N_NODES) {
        int k = i / SCAN_BS;
        int off = s[k] - g_blocksums[k];
        int v = g_rowstart[i] + off;
        g_rowstart[i] = v;
        g_cnt[i] = v;                // cursor for scatter
    }
    if (i == 0) g_rowstart[N_NODES] = N_EDGES;
}

__global__ void scatter_kernel(const int* __restrict__ rows,
                               const int* __restrict__ cols,
                               const float* __restrict__ vals) {
    int e = blockIdx.x * blockDim.x + threadIdx.x;
    if (e >= N_EDGES) return;
    int r = rows[e];
    int pos = atomicAdd(&g_cnt[r], 1);
    g_edge[pos] = make_int2(cols[e], __float_as_int(vals[e]));
}

// ---------------- Layer-2 frontier flags ----------------
__global__ void flagmark_kernel(const int* __restrict__ users,
                                const int* __restrict__ items) {
    int b = blockIdx.x * blockDim.x + threadIdx.x;
    if (b >= SEL) return;
    int r = (b < BATCH) ? users[b] : N_USER + items[b - BATCH];
    g_flag[r] = 1;
    int s = g_rowstart[r], e = g_rowstart[r + 1];
    for (int j = s; j < e; j++) g_flag[g_edge[j].x] = 1;
}

// ---------------- SpMM core: 16 lanes per row, half4 per lane, fp32 acc ------
__device__ __forceinline__ float4 row_reduce_h(const uint2* __restrict__ in,
                                               int s, int e, int lane) {
    float4 a = make_float4(0.f, 0.f, 0.f, 0.f);
    int j = s;
    for (; j + 4 <= e; j += 4) {
        int2 E0 = g_edge[j], E1 = g_edge[j + 1], E2 = g_edge[j + 2], E3 = g_edge[j + 3];
        uint2 u0 = in[(size_t)E0.x * 16 + lane];
        uint2 u1 = in[(size_t)E1.x * 16 + lane];
        uint2 u2 = in[(size_t)E2.x * 16 + lane];
        uint2 u3 = in[(size_t)E3.x * 16 + lane];
        float v0 = __int_as_float(E0.y), v1 = __int_as_float(E1.y);
        float v2 = __int_as_float(E2.y), v3 = __int_as_float(E3.y);
        float2 f;
        f = __half22float2(*reinterpret_cast<__half2*>(&u0.x)); a.x += v0 * f.x; a.y += v0 * f.y;
        f = __half22float2(*reinterpret_cast<__half2*>(&u0.y)); a.z += v0 * f.x; a.w += v0 * f.y;
        f = __half22float2(*reinterpret_cast<__half2*>(&u1.x)); a.x += v1 * f.x; a.y += v1 * f.y;
        f = __half22float2(*reinterpret_cast<__half2*>(&u1.y)); a.z += v1 * f.x; a.w += v1 * f.y;
        f = __half22float2(*reinterpret_cast<__half2*>(&u2.x)); a.x += v2 * f.x; a.y += v2 * f.y;
        f = __half22float2(*reinterpret_cast<__half2*>(&u2.y)); a.z += v2 * f.x; a.w += v2 * f.y;
        f = __half22float2(*reinterpret_cast<__half2*>(&u3.x)); a.x += v3 * f.x; a.y += v3 * f.y;
        f = __half22float2(*reinterpret_cast<__half2*>(&u3.y)); a.z += v3 * f.x; a.w += v3 * f.y;
    }
    for (; j < e; j++) {
        int2 E = g_edge[j];
        uint2 u = in[(size_t)E.x * 16 + lane];
        float v = __int_as_float(E.y);
        float2 f;
        f = __half22float2(*reinterpret_cast<__half2*>(&u.x)); a.x += v * f.x; a.y += v * f.y;
        f = __half22float2(*reinterpret_cast<__half2*>(&u.y)); a.z += v * f.x; a.w += v * f.y;
    }
    return a;
}

__device__ __forceinline__ uint2 pack_half4(float4 a) {
    __half2 h0 = __float22half2_rn(make_float2(a.x, a.y));
    __half2 h1 = __float22half2_rn(make_float2(a.z, a.w));
    uint2 p;
    p.x = *reinterpret_cast<unsigned*>(&h0);
    p.y = *reinterpret_cast<unsigned*>(&h1);
    return p;
}

// Layer 1: all nodes, gather from g_emb_h, write g_e1h.
__global__ void spmm1_kernel() {
    int gid = blockIdx.x * blockDim.x + threadIdx.x;
    int row = gid >> 4, lane = gid & 15;
    if (row >= N_NODES) return;
    int s = g_rowstart[row], e = g_rowstart[row + 1];
    float4 a = row_reduce_h((const uint2*)g_emb_h, s, e, lane);
    ((uint2*)g_e1h)[(size_t)row * 16 + lane] = pack_half4(a);
}

// Layer 2: flagged rows only.
__global__ void spmm2_kernel() {
    int gid = blockIdx.x * blockDim.x + threadIdx.x;
    int row = gid >> 4, lane = gid & 15;
    if (row >= N_NODES) return;
    if (!g_flag[row]) return;
    int s = g_rowstart[row], e = g_rowstart[row + 1];
    float4 a = row_reduce_h((const uint2*)g_e1h, s, e, lane);
    ((uint2*)g_e2h)[(size_t)row * 16 + lane] = pack_half4(a);
}

// Layer 3 + layer-mean combine, selected nodes only, compact output.
__global__ void spmm3_combine_kernel(const float4* __restrict__ ue,
                                     const float4* __restrict__ ie,
                                     const int* __restrict__ users,
                                     const int* __restrict__ items) {
    int gid = blockIdx.x * blockDim.x + threadIdx.x;
    int b = gid >> 4, lane = gid & 15;
    if (b >= SEL) return;
    int row; float4 e0;
    if (b < BATCH) { int u = users[b]; row = u; e0 = ue[(size_t)u * 16 + lane]; }
    else { int it = items[b - BATCH]; row = N_USER + it; e0 = ie[(size_t)it * 16 + lane]; }
    int s = g_rowstart[row], e = g_rowstart[row + 1];
    float4 e3 = row_reduce_h((const uint2*)g_e2h, s, e, lane);

    uint2 u1 = ((const uint2*)g_e1h)[(size_t)row * 16 + lane];
    uint2 u2 = ((const uint2*)g_e2h)[(size_t)row * 16 + lane];
    float2 a1 = __half22float2(*reinterpret_cast<__half2*>(&u1.x));
    float2 b1 = __half22float2(*reinterpret_cast<__half2*>(&u1.y));
    float2 a2 = __half22float2(*reinterpret_cast<__half2*>(&u2.x));
    float2 b2 = __half22float2(*reinterpret_cast<__half2*>(&u2.y));

    float4 o;
    o.x = 0.25f * (e0.x + a1.x + a2.x + e3.x);
    o.y = 0.25f * (e0.y + a1.y + a2.y + e3.y);
    o.z = 0.25f * (e0.z + b1.x + b2.x + e3.z);
    o.w = 0.25f * (e0.w + b1.y + b2.y + e3.w);
    ((float4*)g_sel)[(size_t)b * 16 + lane] = o;
}

// ---------------- GEMM (u @ i.T) + sigmoid ----------------
__global__ void bpr_out_kernel(float* __restrict__ out) {
    __shared__ float Us[64][68];
    __shared__ float Is[64][68];
    int t   = threadIdx.x;
    int bu0 = blockIdx.y * 64;
    int bi0 = blockIdx.x * 64;

    const float4* sel4 = (const float4*)g_sel;
    #pragma unroll
    for (int i = 0; i < 4; i++) {
        int idx = t + i * 256;
        int r   = idx >> 4;
        int kq  = idx & 15;
        *(float4*)&Us[r][kq * 4] = sel4[(size_t)(bu0 + r) * 16 + kq];
        *(float4*)&Is[r][kq * 4] = sel4[(size_t)(BATCH + bi0 + r) * 16 + kq];
    }
    __syncthreads();

    int tx = t & 15, ty = t >> 4;
    float acc[4][4];
    #pragma unroll
    for (int r = 0; r < 4; r++)
        #pragma unroll
        for (int c = 0; c < 4; c++) acc[r][c] = 0.f;

    #pragma unroll
    for (int k = 0; k < 64; k += 4) {
        float4 a[4], b[4];
        #pragma unroll
        for (int r = 0; r < 4; r++) a[r] = *(const float4*)&Us[ty * 4 + r][k];
        #pragma unroll
        for (int c = 0; c < 4; c++) b[c] = *(const float4*)&Is[tx * 4 + c][k];
        #pragma unroll
        for (int r = 0; r < 4; r++)
            #pragma unroll
            for (int c = 0; c < 4; c++)
                acc[r][c] += a[r].x * b[c].x + a[r].y * b[c].y
                           + a[r].z * b[c].z + a[r].w * b[c].w;
    }

    #pragma unroll
    for (int r = 0; r < 4; r++) {
        int orow = bu0 + ty * 4 + r;
        float4 o;
        o.x = 1.f / (1.f + expf(-acc[r][0]));
        o.y = 1.f / (1.f + expf(-acc[r][1]));
        o.z = 1.f / (1.f + expf(-acc[r][2]));
        o.w = 1.f / (1.f + expf(-acc[r][3]));
        *(float4*)&out[(size_t)orow * BATCH + bi0 + tx * 4] = o;
    }
}

// ---------------- launch ----------------
extern "C" void kernel_launch(void* const* d_in, const int* in_sizes, int n_in,
                              void* d_out, int out_size) {
    const float* user_emb = (const float*)d_in[0];
    const float* item_emb = (const float*)d_in[1];
    const float* adj_vals = (const float*)d_in[2];
    const int*   adj_rows = (const int*)d_in[3];
    const int*   adj_cols = (const int*)d_in[4];
    const int*   users    = (const int*)d_in[5];
    const int*   items    = (const int*)d_in[6];
    float*       out      = (float*)d_out;

    // zero counters + fp16 convert
    zero_convert_kernel<<<(N_NODES * 16 + 255) / 256, 256>>>(
        (const float4*)user_emb, (const float4*)item_emb);

    // CSR build
    hist_kernel<<<(N_EDGES / 4 + 255) / 256, 256>>>((const int4*)adj_rows);
    scanA_kernel<<<NBLK_SCAN, SCAN_BS>>>();
    scanC_kernel<<<(N_NODES + 255) / 256, 256>>>();
    scatter_kernel<<<(N_EDGES + 255) / 256, 256>>>(adj_rows, adj_cols, adj_vals);

    // Layer 1: full
    spmm1_kernel<<<(N_NODES * 16 + 255) / 256, 256>>>();
    // Frontier flags for layer 2
    flagmark_kernel<<<(SEL + 255) / 256, 256>>>(users, items);
    // Layer 2: flagged rows only
    spmm2_kernel<<<(N_NODES * 16 + 255) / 256, 256>>>();
    // Layer 3 + combine: selected nodes only
    spmm3_combine_kernel<<<(SEL * 16) / 256, 256>>>(
        (const float4*)user_emb, (const float4*)item_emb, users, items);

    // Output GEMM + sigmoid
    {
        dim3 grid(BATCH / 64, BATCH / 64);
        bpr_out_kernel<<<grid, 256>>>(out);
    }
}